// round 5
// baseline (speedup 1.0000x reference)
#include <cuda_runtime.h>
#include <cuda_bf16.h>

#define MAX_NODES 65536
#define MAX_MSGS  (1 << 21)   // capacity 2M messages (workload: 1M)

__device__ int g_counts[MAX_NODES];   // per-node message count
__device__ int g_offsets[MAX_NODES];  // exclusive prefix sum of counts
__device__ int g_cursor[MAX_NODES];   // scatter cursors (init = offsets)
__device__ int g_sorted[MAX_MSGS];    // message indices grouped by node
__device__ int g_ids_is64;

// ---------------------------------------------------------------------------
// init: (a) detect id width with 64 warp-parallel probes (int32 data read as
// int64 fuses two random ids -> value outside [0, 2^31) almost surely),
// (b) zero the count table.
// ---------------------------------------------------------------------------
__global__ void init_kernel(const long long* __restrict__ p64, int n64, int num_nodes)
{
    if (blockIdx.x == 0 && threadIdx.x < 32) {
        int ok = 1;
        #pragma unroll
        for (int k = 0; k < 2; ++k) {
            long long pos = ((long long)(threadIdx.x * 2 + k) * n64) / 64;
            if (pos < n64) {
                long long v = p64[pos];
                if (v < 0 || v >= (1LL << 31)) ok = 0;
            }
        }
        unsigned m = __ballot_sync(0xFFFFFFFFu, ok);
        if (threadIdx.x == 0) g_ids_is64 = (m == 0xFFFFFFFFu) ? 1 : 0;
    }
    for (int i = blockIdx.x * blockDim.x + threadIdx.x; i < num_nodes;
         i += gridDim.x * blockDim.x)
        g_counts[i] = 0;
}

// ---------------------------------------------------------------------------
// Histogram: count messages per node. 1M int atomics spread over 50K
// addresses -> far below the LTS atomic-ALU serialization regime.
// ---------------------------------------------------------------------------
__global__ void __launch_bounds__(256)
hist_kernel(const void* __restrict__ ids, int M)
{
    int is64 = g_ids_is64;
    for (int m = blockIdx.x * blockDim.x + threadIdx.x; m < M;
         m += gridDim.x * blockDim.x) {
        int node = is64 ? (int)((const long long*)ids)[m]
                        : ((const int*)ids)[m];
        atomicAdd(&g_counts[node], 1);
    }
}

// ---------------------------------------------------------------------------
// Exclusive scan over counts (single block). Each thread sequentially sums a
// contiguous chunk, a two-level shuffle scan combines the 1024 partials
// (3 barriers total), then each thread writes its chunk's running offsets.
// Cursors are initialized to the offsets here.
// ---------------------------------------------------------------------------
__global__ void __launch_bounds__(1024)
scan_kernel(int num_nodes)
{
    const int T = 1024;
    __shared__ int warp_sums[32];

    int chunk = (num_nodes + T - 1) / T;
    int start = threadIdx.x * chunk;
    int end   = start + chunk < num_nodes ? start + chunk : num_nodes;

    int local = 0;
    for (int i = start; i < end; ++i) local += g_counts[i];

    int lane = threadIdx.x & 31, wid = threadIdx.x >> 5;
    int v = local;
    #pragma unroll
    for (int s = 1; s < 32; s <<= 1) {
        int t = __shfl_up_sync(0xFFFFFFFFu, v, s);
        if (lane >= s) v += t;
    }
    if (lane == 31) warp_sums[wid] = v;
    __syncthreads();
    if (wid == 0) {
        int w = warp_sums[lane];
        #pragma unroll
        for (int s = 1; s < 32; s <<= 1) {
            int t = __shfl_up_sync(0xFFFFFFFFu, w, s);
            if (lane >= s) w += t;
        }
        warp_sums[lane] = w;
    }
    __syncthreads();

    int excl = v - local + (wid > 0 ? warp_sums[wid - 1] : 0);
    int run = excl;
    for (int i = start; i < end; ++i) {
        int c = g_counts[i];
        g_offsets[i] = run;
        g_cursor[i]  = run;
        run += c;
    }
}

// ---------------------------------------------------------------------------
// Scatter message INDICES (4B each, not 512B payloads) into node buckets.
// ---------------------------------------------------------------------------
__global__ void __launch_bounds__(256)
scatter_idx_kernel(const void* __restrict__ ids, int M)
{
    int is64 = g_ids_is64;
    for (int m = blockIdx.x * blockDim.x + threadIdx.x; m < M;
         m += gridDim.x * blockDim.x) {
        int node = is64 ? (int)((const long long*)ids)[m]
                        : ((const int*)ids)[m];
        int slot = atomicAdd(&g_cursor[node], 1);
        g_sorted[slot] = m;
    }
}

// ---------------------------------------------------------------------------
// Gather-mean: one warp per node. Each lane owns 4 of the 128 dims (float4).
// Unrolled-by-4 main loop gives MLP=4 independent 512B row reads. Divide by
// count once, write the mean directly (no atomics, no zero, no finalize;
// empty nodes emit exact zeros). Lane 0 also writes unique_node_ids.
// ---------------------------------------------------------------------------
__global__ void __launch_bounds__(256)
gather_kernel(const float* __restrict__ msgs, float* __restrict__ agg,
              float* __restrict__ ids_out, int num_nodes, int write_ids)
{
    int warp = (blockIdx.x * blockDim.x + threadIdx.x) >> 5;
    int lane = threadIdx.x & 31;
    if (warp >= num_nodes) return;

    int cnt = g_counts[warp];
    int off = g_offsets[warp];

    float4 acc = make_float4(0.f, 0.f, 0.f, 0.f);

    int j = 0;
    for (; j + 4 <= cnt; j += 4) {
        int i0 = __ldg(&g_sorted[off + j + 0]);
        int i1 = __ldg(&g_sorted[off + j + 1]);
        int i2 = __ldg(&g_sorted[off + j + 2]);
        int i3 = __ldg(&g_sorted[off + j + 3]);
        float4 a = __ldg((const float4*)(msgs + (size_t)i0 * 128) + lane);
        float4 b = __ldg((const float4*)(msgs + (size_t)i1 * 128) + lane);
        float4 c = __ldg((const float4*)(msgs + (size_t)i2 * 128) + lane);
        float4 d = __ldg((const float4*)(msgs + (size_t)i3 * 128) + lane);
        float4 s0, s1;
        s0.x = a.x + b.x; s0.y = a.y + b.y; s0.z = a.z + b.z; s0.w = a.w + b.w;
        s1.x = c.x + d.x; s1.y = c.y + d.y; s1.z = c.z + d.z; s1.w = c.w + d.w;
        acc.x += s0.x + s1.x; acc.y += s0.y + s1.y;
        acc.z += s0.z + s1.z; acc.w += s0.w + s1.w;
    }
    for (; j < cnt; ++j) {
        int i0 = __ldg(&g_sorted[off + j]);
        float4 a = __ldg((const float4*)(msgs + (size_t)i0 * 128) + lane);
        acc.x += a.x; acc.y += a.y; acc.z += a.z; acc.w += a.w;
    }

    float inv = 1.0f / fmaxf((float)cnt, 1.0f);
    acc.x *= inv; acc.y *= inv; acc.z *= inv; acc.w *= inv;

    ((float4*)(agg + (size_t)warp * 128))[lane] = acc;

    if (write_ids && lane == 0) ids_out[warp] = (float)warp;
}

extern "C" void kernel_launch(void* const* d_in, const int* in_sizes, int n_in,
                              void* d_out, int out_size)
{
    const void*  ids  = d_in[0];
    const float* msgs = (const float*)d_in[1];

    const int D = 128;
    int M = in_sizes[1] / D;
    if (M > MAX_MSGS) M = MAX_MSGS;

    // Output layout: N*129 -> [arange ids | N x 128 agg]; N*128 -> agg only.
    int num_nodes, write_ids;
    if (out_size % 129 == 0) { num_nodes = out_size / 129; write_ids = 1; }
    else                     { num_nodes = out_size / 128; write_ids = 0; }
    if (num_nodes > MAX_NODES) num_nodes = MAX_NODES;

    float* outf    = (float*)d_out;
    float* ids_out = outf;
    float* agg     = write_ids ? (outf + num_nodes) : outf;

    int n64_safe = M / 2;  // valid int64-word count even if data is int32

    {
        int blocks = (num_nodes + 255) / 256;
        init_kernel<<<blocks, 256>>>((const long long*)ids, n64_safe, num_nodes);
    }
    {
        int blocks = (M + 255) / 256;
        hist_kernel<<<blocks, 256>>>(ids, M);
    }
    scan_kernel<<<1, 1024>>>(num_nodes);
    {
        int blocks = (M + 255) / 256;
        scatter_idx_kernel<<<blocks, 256>>>(ids, M);
    }
    {
        int blocks = (num_nodes * 32 + 255) / 256;
        gather_kernel<<<blocks, 256>>>(msgs, agg, ids_out, num_nodes, write_ids);
    }
}

// round 6
// speedup vs baseline: 1.5124x; 1.5124x over previous
#include <cuda_runtime.h>
#include <cuda_bf16.h>

#define MAX_NODES 65536

__device__ float g_counts[MAX_NODES];
__device__ int   g_ids_is64;

// ---------------------------------------------------------------------------
// init: (a) warp 0 of block 0 detects id width (int32 data read as int64 fuses
// two random ids -> value outside [0, 2^31) almost surely; 64 probes),
// (b) zero counts and the sum accumulator (float4 stores).
// ---------------------------------------------------------------------------
__global__ void init_kernel(const long long* __restrict__ p64, int n64,
                            float4* __restrict__ agg4, int num_nodes)
{
    if (blockIdx.x == 0 && threadIdx.x < 32) {
        int ok = 1;
        #pragma unroll
        for (int k = 0; k < 2; ++k) {
            long long pos = ((long long)(threadIdx.x * 2 + k) * n64) / 64;
            if (pos < n64) {
                long long v = p64[pos];
                if (v < 0 || v >= (1LL << 31)) ok = 0;
            }
        }
        unsigned m = __ballot_sync(0xFFFFFFFFu, ok);
        if (threadIdx.x == 0) g_ids_is64 = (m == 0xFFFFFFFFu) ? 1 : 0;
    }
    int total4 = num_nodes * 32;  // 128 floats = 32 float4 per node
    const float4 z = make_float4(0.f, 0.f, 0.f, 0.f);
    for (int i = blockIdx.x * blockDim.x + threadIdx.x; i < total4;
         i += gridDim.x * blockDim.x) {
        agg4[i] = z;
        if (i < num_nodes) g_counts[i] = 0.0f;
    }
}

// ---------------------------------------------------------------------------
// Scatter-add: one warp per FOUR messages. Per iteration the warp issues 4
// independent id loads (same L2 line, broadcast), 4 independent LDG.128 row
// loads (512B each, fully coalesced, streamed with __ldcs so the 512MB
// message stream does NOT evict the 25.6MB L2-resident sum table), then 4
// red.global.add.v4.f32 ops. Lane 0 bumps the 4 per-node counts.
// ---------------------------------------------------------------------------
__device__ __forceinline__ void red_v4(float* dst, float4 v)
{
    asm volatile("red.global.add.v4.f32 [%0], {%1, %2, %3, %4};"
                 :: "l"(dst), "f"(v.x), "f"(v.y), "f"(v.z), "f"(v.w)
                 : "memory");
}
__device__ __forceinline__ void red_f(float* dst)
{
    asm volatile("red.global.add.f32 [%0], %1;"
                 :: "l"(dst), "f"(1.0f) : "memory");
}

__global__ void __launch_bounds__(256)
scatter_kernel(const void* __restrict__ ids_raw,
               const float* __restrict__ msgs,
               float* __restrict__ sums,
               int num_messages)
{
    int warp = (blockIdx.x * blockDim.x + threadIdx.x) >> 5;
    int lane = threadIdx.x & 31;
    int base = warp << 2;
    if (base >= num_messages) return;
    int is64 = g_ids_is64;

    if (base + 4 <= num_messages) {
        int n0, n1, n2, n3;
        if (is64) {
            const long long* p = (const long long*)ids_raw + base;
            n0 = (int)__ldg(p + 0); n1 = (int)__ldg(p + 1);
            n2 = (int)__ldg(p + 2); n3 = (int)__ldg(p + 3);
        } else {
            const int* p = (const int*)ids_raw + base;
            n0 = __ldg(p + 0); n1 = __ldg(p + 1);
            n2 = __ldg(p + 2); n3 = __ldg(p + 3);
        }
        const float4* r0 = (const float4*)(msgs + (size_t)(base + 0) * 128) + lane;
        const float4* r1 = (const float4*)(msgs + (size_t)(base + 1) * 128) + lane;
        const float4* r2 = (const float4*)(msgs + (size_t)(base + 2) * 128) + lane;
        const float4* r3 = (const float4*)(msgs + (size_t)(base + 3) * 128) + lane;
        float4 v0 = __ldcs(r0);
        float4 v1 = __ldcs(r1);
        float4 v2 = __ldcs(r2);
        float4 v3 = __ldcs(r3);

        red_v4(sums + (size_t)n0 * 128 + lane * 4, v0);
        red_v4(sums + (size_t)n1 * 128 + lane * 4, v1);
        red_v4(sums + (size_t)n2 * 128 + lane * 4, v2);
        red_v4(sums + (size_t)n3 * 128 + lane * 4, v3);

        if (lane == 0) {
            red_f(&g_counts[n0]); red_f(&g_counts[n1]);
            red_f(&g_counts[n2]); red_f(&g_counts[n3]);
        }
    } else {
        for (int m = base; m < num_messages; ++m) {
            int node = is64 ? (int)((const long long*)ids_raw)[m]
                            : ((const int*)ids_raw)[m];
            float4 v = __ldcs((const float4*)(msgs + (size_t)m * 128) + lane);
            red_v4(sums + (size_t)node * 128 + lane * 4, v);
            if (lane == 0) red_f(&g_counts[node]);
        }
    }
}

// ---------------------------------------------------------------------------
// Finalize: one warp per node. One uniform count load per warp, each lane
// rescales one float4 of the row (LDG.128 + STG.128, fully coalesced).
// Lane 0 also writes unique_node_ids = arange (exact in fp32 up to 2^24).
// ---------------------------------------------------------------------------
__global__ void __launch_bounds__(256)
finalize_kernel(float* __restrict__ agg, float* __restrict__ ids_out,
                int num_nodes, int write_ids)
{
    int warp = (blockIdx.x * blockDim.x + threadIdx.x) >> 5;
    int lane = threadIdx.x & 31;
    if (warp >= num_nodes) return;

    float c   = g_counts[warp];                 // uniform
    float inv = 1.0f / fmaxf(c, 1.0f);

    float4* row = (float4*)(agg + (size_t)warp * 128) + lane;
    float4 v = *row;
    v.x *= inv; v.y *= inv; v.z *= inv; v.w *= inv;
    *row = v;

    if (write_ids && lane == 0) ids_out[warp] = (float)warp;
}

extern "C" void kernel_launch(void* const* d_in, const int* in_sizes, int n_in,
                              void* d_out, int out_size)
{
    const void*  ids  = d_in[0];
    const float* msgs = (const float*)d_in[1];

    const int D = 128;
    int M = in_sizes[1] / D;

    // Output layout: N*129 -> [arange ids | N x 128 agg]; N*128 -> agg only.
    int num_nodes, write_ids;
    if (out_size % 129 == 0) { num_nodes = out_size / 129; write_ids = 1; }
    else                     { num_nodes = out_size / 128; write_ids = 0; }
    if (num_nodes > MAX_NODES) num_nodes = MAX_NODES;

    float* outf    = (float*)d_out;
    float* ids_out = outf;
    float* agg     = write_ids ? (outf + num_nodes) : outf;

    int n64_safe = M / 2;  // valid int64-word count even if data is int32

    {
        int total4 = num_nodes * 32;
        int blocks = (total4 + 255) / 256;
        if (blocks > 8192) blocks = 8192;
        init_kernel<<<blocks, 256>>>((const long long*)ids, n64_safe,
                                     (float4*)agg, num_nodes);
    }
    {
        int warps  = (M + 3) / 4;             // one warp per 4 messages
        int blocks = (warps * 32 + 255) / 256;
        scatter_kernel<<<blocks, 256>>>(ids, msgs, agg, M);
    }
    {
        int blocks = (num_nodes * 32 + 255) / 256;
        finalize_kernel<<<blocks, 256>>>(agg, ids_out, num_nodes, write_ids);
    }
}